// round 2
// baseline (speedup 1.0000x reference)
#include <cuda_runtime.h>
#include <cstdint>

// EdgeFeature: B=4, D=64, N=4096, K=16
// out = [ edge_feature (4,128,4096,16) fp32 ; idx (4,65536) as fp32 ]

#define B_ 4
#define D_ 64
#define N_ 4096
#define K_ 16

// Scratch (static __device__ — no allocations allowed in kernel_launch)
__device__ float g_sq[B_ * N_];                       // 64 KB
__device__ float g_dist[(size_t)B_ * N_ * N_];        // 256 MB (fp32 dist, post-sqrt)
__device__ int   g_idx[B_ * N_ * K_];                 // 1 MB

// ---------------------------------------------------------------------------
// 1) squared norms: sq[b][n] = sum_d pc[b][d][n]^2  (sequential ascending d,
//    fmaf — matches the dot-product accumulation order in d2_kernel so the
//    self-distance cancels to exactly 0.0f)
// ---------------------------------------------------------------------------
__global__ void sq_kernel(const float* __restrict__ pc) {
    int gid = blockIdx.x * blockDim.x + threadIdx.x;   // 16384 threads
    int b = gid >> 12;
    int n = gid & (N_ - 1);
    const float* X = pc + (size_t)b * D_ * N_;
    float acc = 0.0f;
    #pragma unroll
    for (int d = 0; d < D_; d++) {
        float v = X[d * N_ + n];
        acc = fmaf(v, v, acc);
    }
    g_sq[gid] = acc;
}

// ---------------------------------------------------------------------------
// 2) dist[b][i][j] = sqrt(max(sq_i + sq_j - 2*dot(x_i, x_j), 0))
//    128x128 CTA tile, 256 threads, 8x8 micro-tile, K=64 in two 32-deep chunks
//    Ranking is done on dist (matching the reference's top_k(-dist)), so the
//    sqrt is applied HERE and dist is what goes to scratch.
// ---------------------------------------------------------------------------
__global__ __launch_bounds__(256, 2) void d2_kernel(const float* __restrict__ pc) {
    __shared__ float As[32][128];
    __shared__ float Bs[32][128];
    __shared__ float sqa[128];
    __shared__ float sqb[128];

    int b  = blockIdx.z;
    int i0 = blockIdx.y * 128;
    int j0 = blockIdx.x * 128;
    const float* X = pc + (size_t)b * D_ * N_;
    int t = threadIdx.x;

    if (t < 128) sqa[t]       = g_sq[b * N_ + i0 + t];
    else         sqb[t - 128] = g_sq[b * N_ + j0 + (t - 128)];

    int r = t >> 4;    // 0..15 (row group)
    int c = t & 15;    // 0..15 (col group)

    float acc[8][8];
    #pragma unroll
    for (int ii = 0; ii < 8; ii++)
        #pragma unroll
        for (int jj = 0; jj < 8; jj++)
            acc[ii][jj] = 0.0f;

    for (int dc = 0; dc < D_; dc += 32) {
        __syncthreads();   // protect smem reuse (and sqa/sqb on first pass)
        // load 32x128 tiles of A (rows i0..) and B (rows j0..), float4s
        for (int l = t; l < 1024; l += 256) {
            int d  = l >> 5;
            int i4 = (l & 31) << 2;
            *(float4*)&As[d][i4] = *(const float4*)&X[(size_t)(dc + d) * N_ + i0 + i4];
            *(float4*)&Bs[d][i4] = *(const float4*)&X[(size_t)(dc + d) * N_ + j0 + i4];
        }
        __syncthreads();

        #pragma unroll 8
        for (int d = 0; d < 32; d++) {
            float a[8], bb[8];
            *(float4*)&a[0]  = *(float4*)&As[d][r * 8];
            *(float4*)&a[4]  = *(float4*)&As[d][r * 8 + 4];
            *(float4*)&bb[0] = *(float4*)&Bs[d][c * 8];
            *(float4*)&bb[4] = *(float4*)&Bs[d][c * 8 + 4];
            #pragma unroll
            for (int ii = 0; ii < 8; ii++)
                #pragma unroll
                for (int jj = 0; jj < 8; jj++)
                    acc[ii][jj] = fmaf(a[ii], bb[jj], acc[ii][jj]);
        }
    }

    // epilogue: dist = sqrt(clamp(sq_i + sq_j - 2*dot, 0)), write to scratch.
    // Note 2*acc is exact in fp32, so s - 2*acc has identical rounding whether
    // or not the compiler contracts it to an FMA -> matches the reference.
    #pragma unroll
    for (int ii = 0; ii < 8; ii++) {
        int   row = i0 + r * 8 + ii;
        float si  = sqa[r * 8 + ii];
        float* dst = g_dist + ((size_t)(b * N_ + row) << 12) + j0 + c * 8;
        float v[8];
        #pragma unroll
        for (int jj = 0; jj < 8; jj++) {
            float s = si + sqb[c * 8 + jj];
            v[jj] = sqrtf(fmaxf(s - 2.0f * acc[ii][jj], 0.0f));
        }
        *(float4*)&dst[0] = *(float4*)&v[0];
        *(float4*)&dst[4] = *(float4*)&v[4];
    }
}

// ---------------------------------------------------------------------------
// 3) per-row top-(K+1) selection on dist, drop rank 0 (self: dist == 0).
//    Lexicographic key (dist_bits << 32) | j reproduces lax.top_k's stable
//    lower-index tie-break AT THE dist (post-sqrt) LEVEL, exactly like the
//    reference. 17 iterative block argmin passes.
// ---------------------------------------------------------------------------
__global__ __launch_bounds__(256) void select_kernel(float* __restrict__ out_idx_f) {
    __shared__ float vals[N_];
    __shared__ unsigned long long wred[8];

    int row = blockIdx.x;                      // b*4096 + i
    const float* src = g_dist + (size_t)row * N_;
    int t = threadIdx.x;
    int lane = t & 31, w = t >> 5;

    for (int l = t; l < N_ / 4; l += 256)
        ((float4*)vals)[l] = ((const float4*)src)[l];
    __syncthreads();

    for (int p = 0; p <= K_; p++) {
        unsigned long long best = 0xFFFFFFFFFFFFFFFFull;
        #pragma unroll
        for (int jj = 0; jj < 16; jj++) {
            int j = t + jj * 256;
            unsigned long long key =
                ((unsigned long long)__float_as_uint(vals[j]) << 32) | (unsigned)j;
            best = (key < best) ? key : best;
        }
        #pragma unroll
        for (int off = 16; off; off >>= 1) {
            unsigned long long o = __shfl_down_sync(0xffffffffu, best, off);
            best = (o < best) ? o : best;
        }
        if (lane == 0) wred[w] = best;
        __syncthreads();
        if (t == 0) {
            unsigned long long bb = wred[0];
            #pragma unroll
            for (int q = 1; q < 8; q++) bb = (wred[q] < bb) ? wred[q] : bb;
            int win = (int)(bb & 0xFFFFFFFFu);
            if (p > 0) {
                g_idx[row * K_ + (p - 1)]     = win;
                out_idx_f[row * K_ + (p - 1)] = (float)win;
            }
            vals[win] = __int_as_float(0x7F800000);   // +inf: remove from pool
        }
        __syncthreads();
    }
}

// ---------------------------------------------------------------------------
// 4) gather + concat epilogue.
//    Block = (b, 32-wide n tile); for each channel c, the 32x16 (n,k) slab is
//    contiguous in the output -> fully coalesced 1 KB stores. Gathers hit L2
//    (point cloud is 4 MB total).
// ---------------------------------------------------------------------------
__global__ __launch_bounds__(256) void gather_kernel(const float* __restrict__ pc,
                                                     float* __restrict__ out) {
    __shared__ int   sidx[32 * K_];
    __shared__ float cen[D_][32];

    int blk = blockIdx.x;             // 512 blocks
    int b   = blk >> 7;               // 128 n-tiles per batch
    int n0  = (blk & 127) * 32;
    int t   = threadIdx.x;
    const float* pcb = pc + (size_t)b * D_ * N_;

    for (int l = t; l < 32 * K_; l += 256)
        sidx[l] = g_idx[(b * N_ + n0) * K_ + l];
    for (int l = t; l < D_ * 32; l += 256) {
        int d = l >> 5, n = l & 31;
        cen[d][n] = pcb[d * N_ + n0 + n];
    }
    __syncthreads();

    size_t obase = (size_t)b * 2 * D_ * N_ * K_;
    #pragma unroll 4
    for (int c = 0; c < D_; c++) {
        #pragma unroll
        for (int q = 0; q < 2; q++) {
            int l = t + q * 256;          // 512 (n,k) pairs
            int n = l >> 4, k = l & 15;
            float ce = cen[c][n];
            float nb = __ldg(&pcb[c * N_ + sidx[l]]);
            size_t o = obase + ((size_t)c * N_ + n0 + n) * K_ + k;
            out[o]                          = ce;        // central channels 0..63
            out[o + (size_t)D_ * N_ * K_]   = nb - ce;   // neighbor-central 64..127
        }
    }
}

// ---------------------------------------------------------------------------
extern "C" void kernel_launch(void* const* d_in, const int* in_sizes, int n_in,
                              void* d_out, int out_size) {
    const float* pc = (const float*)d_in[0];
    float* out = (float*)d_out;
    float* out_idx = out + (size_t)B_ * 2 * D_ * N_ * K_;   // 33,554,432 floats in

    sq_kernel<<<(B_ * N_) / 256, 256>>>(pc);
    dim3 gg(N_ / 128, N_ / 128, B_);
    d2_kernel<<<gg, 256>>>(pc);
    select_kernel<<<B_ * N_, 256>>>(out_idx);
    gather_kernel<<<(B_ * N_) / 32, 256>>>(pc, out);
}